// round 2
// baseline (speedup 1.0000x reference)
#include <cuda_runtime.h>
#include <cuda_bf16.h>

// Problem constants (shapes fixed by the dataset)
#define C_DIM   512
#define OUT_DIM 512
#define K_NEIGH 32
#define MAX_N   20000

// Scratch for the aggregated neighbor means (allocation-free rule: __device__ global)
__device__ float g_agg[(size_t)MAX_N * C_DIM];

// ---------------------------------------------------------------------------
// Kernel 1: agg[n, c] = mean_k neigh_x[n, k, c]
// One CTA per row n; 128 threads, each owns 4 contiguous channels (float4).
// Streams 1.31 GB once; HBM-bound.
// ---------------------------------------------------------------------------
__global__ void mean_kernel(const float* __restrict__ neigh, int M) {
    int n = blockIdx.x;
    if (n >= M) return;
    int c4 = threadIdx.x;  // 0..127, float4 index across C=512
    const float4* base = reinterpret_cast<const float4*>(neigh)
                       + (size_t)n * (K_NEIGH * C_DIM / 4) + c4;
    float4 s = make_float4(0.f, 0.f, 0.f, 0.f);
#pragma unroll
    for (int k = 0; k < K_NEIGH; ++k) {
        float4 v = base[(size_t)k * (C_DIM / 4)];
        s.x += v.x; s.y += v.y; s.z += v.z; s.w += v.w;
    }
    const float inv = 1.0f / (float)K_NEIGH;
    s.x *= inv; s.y *= inv; s.z *= inv; s.w *= inv;
    reinterpret_cast<float4*>(g_agg)[(size_t)n * (C_DIM / 4) + c4] = s;
}

// ---------------------------------------------------------------------------
// Kernel 2: out = x @ W_l^T + agg @ W_r^T + (b_l + b_r)
// Treated as one GEMM: M x 1024 @ 1024 x 512, with the K loop split into
// the (x, W_l) half and the (agg, W_r) half.
// Tiling: BM=128, BN=128, BK=16; 256 threads; 8x8 accumulator per thread.
// ---------------------------------------------------------------------------
#define BM 128
#define BN 128
#define BK 16
#define TM 8
#define TN 8

__global__ __launch_bounds__(256, 2)
void gemm_kernel(const float* __restrict__ x,
                 const float* __restrict__ Wl,
                 const float* __restrict__ Wr,
                 const float* __restrict__ bl,
                 const float* __restrict__ br,
                 float* __restrict__ out, int M) {
    __shared__ float As[BK][BM];
    __shared__ float Bs[BK][BN + 4];

    const int bm = blockIdx.y * BM;
    const int bn = blockIdx.x * BN;
    const int tid = threadIdx.x;          // 0..255
    const int tx = tid & 15;              // 0..15 -> N direction
    const int ty = tid >> 4;              // 0..15 -> M direction

    // Cooperative-load coordinates (float4 along K)
    const int lrow = tid >> 2;            // 0..63
    const int lcol = (tid & 3) * 4;       // 0,4,8,12

    float acc[TM][TN];
#pragma unroll
    for (int i = 0; i < TM; ++i)
#pragma unroll
        for (int j = 0; j < TN; ++j) acc[i][j] = 0.f;

#pragma unroll 1
    for (int half = 0; half < 2; ++half) {
        const float* A = half ? g_agg : x;
        const float* W = half ? Wr : Wl;

#pragma unroll 1
        for (int k0 = 0; k0 < C_DIM; k0 += BK) {
            // --- load A tile (rows of x/agg), stored transposed As[k][m] ---
#pragma unroll
            for (int r = 0; r < 2; ++r) {
                int row = bm + lrow + r * 64;
                float4 v = make_float4(0.f, 0.f, 0.f, 0.f);
                if (row < M)
                    v = *reinterpret_cast<const float4*>(A + (size_t)row * C_DIM + k0 + lcol);
                As[lcol + 0][lrow + r * 64] = v.x;
                As[lcol + 1][lrow + r * 64] = v.y;
                As[lcol + 2][lrow + r * 64] = v.z;
                As[lcol + 3][lrow + r * 64] = v.w;
            }
            // --- load B tile: Bs[k][n] = W[n][k]  (W is OUT x C row-major) ---
#pragma unroll
            for (int r = 0; r < 2; ++r) {
                int n = lrow + r * 64;    // OUT_DIM=512 divisible by BN -> no guard
                float4 v = *reinterpret_cast<const float4*>(
                    W + (size_t)(bn + n) * C_DIM + k0 + lcol);
                Bs[lcol + 0][n] = v.x;
                Bs[lcol + 1][n] = v.y;
                Bs[lcol + 2][n] = v.z;
                Bs[lcol + 3][n] = v.w;
            }
            __syncthreads();

#pragma unroll
            for (int kk = 0; kk < BK; ++kk) {
                float am[TM], bv[TN];
#pragma unroll
                for (int i = 0; i < TM; ++i) am[i] = As[kk][ty * TM + i];
#pragma unroll
                for (int j = 0; j < TN; ++j) bv[j] = Bs[kk][tx * TN + j];
#pragma unroll
                for (int i = 0; i < TM; ++i)
#pragma unroll
                    for (int j = 0; j < TN; ++j)
                        acc[i][j] += am[i] * bv[j];
            }
            __syncthreads();
        }
    }

    // --- epilogue: add combined bias, store ---
    float bias[TN];
#pragma unroll
    for (int j = 0; j < TN; ++j) {
        int n = bn + tx * TN + j;
        bias[j] = bl[n] + br[n];
    }
#pragma unroll
    for (int i = 0; i < TM; ++i) {
        int row = bm + ty * TM + i;
        if (row < M) {
            float* o = out + (size_t)row * OUT_DIM + bn + tx * TN;
            float4 v0 = make_float4(acc[i][0] + bias[0], acc[i][1] + bias[1],
                                    acc[i][2] + bias[2], acc[i][3] + bias[3]);
            float4 v1 = make_float4(acc[i][4] + bias[4], acc[i][5] + bias[5],
                                    acc[i][6] + bias[6], acc[i][7] + bias[7]);
            *reinterpret_cast<float4*>(o)     = v0;
            *reinterpret_cast<float4*>(o + 4) = v1;
        }
    }
}

extern "C" void kernel_launch(void* const* d_in, const int* in_sizes, int n_in,
                              void* d_out, int out_size) {
    const float* x     = (const float*)d_in[0];
    const float* neigh = (const float*)d_in[1];
    const float* Wl    = (const float*)d_in[2];
    const float* bl    = (const float*)d_in[3];
    const float* Wr    = (const float*)d_in[4];
    const float* br    = (const float*)d_in[5];
    float* out         = (float*)d_out;

    const int M = in_sizes[0] / C_DIM;   // 20000

    mean_kernel<<<M, 128>>>(neigh, M);

    dim3 grid(OUT_DIM / BN, (M + BM - 1) / BM);
    gemm_kernel<<<grid, 256>>>(x, Wl, Wr, bl, br, out, M);
}

// round 9
// speedup vs baseline: 2.0713x; 2.0713x over previous
#include <cuda_runtime.h>
#include <cstdint>
#include <cstddef>

#define C_DIM   512
#define OUT_DIM 512
#define K_NEIGH 32
#define MAX_N   20000

// Scratch (allocation-free rule: __device__ global)
__device__ float g_agg[(size_t)MAX_N * C_DIM];

// ---------------------------------------------------------------------------
// Kernel 1: agg[n,c] = mean_k neigh[n,k,c]   (HBM-bound, streams 1.31 GB)
// ---------------------------------------------------------------------------
__global__ void mean_kernel(const float* __restrict__ neigh, int M) {
    int n = blockIdx.x;
    if (n >= M) return;
    int c4 = threadIdx.x;  // 0..127
    const float4* base = reinterpret_cast<const float4*>(neigh)
                       + (size_t)n * (K_NEIGH * C_DIM / 4) + c4;
    float4 s = make_float4(0.f, 0.f, 0.f, 0.f);
#pragma unroll
    for (int k = 0; k < K_NEIGH; ++k) {
        float4 v = base[(size_t)k * (C_DIM / 4)];
        s.x += v.x; s.y += v.y; s.z += v.z; s.w += v.w;
    }
    const float inv = 1.0f / (float)K_NEIGH;
    s.x *= inv; s.y *= inv; s.z *= inv; s.w *= inv;
    reinterpret_cast<float4*>(g_agg)[(size_t)n * (C_DIM / 4) + c4] = s;
}

// ---------------------------------------------------------------------------
// Kernel 2: tensor-core tf32 GEMM via mma.sync (m16n8k8).
//   out = [x | agg] @ [Wl | Wr]^T + (bl + br)
// CTA tile 128x128, BK=32, 3-stage cp.async ring, 8 warps (2x4), warp 64x32.
// Smem rows padded to 36 floats -> conflict-free fragment LDS.
// ---------------------------------------------------------------------------
#define BM 128
#define BN 128
#define BK 32
#define PAD_K 36                       // floats per smem row (144 B)
#define MAT_B   (BM * PAD_K * 4)       // 18432 B per matrix
#define STAGE_B (2 * MAT_B)            // 36864 B per stage
#define OFF_BIAS (3 * STAGE_B)         // 110592
#define SMEM_TOTAL (OFF_BIAS + BN * 4) // 111104

__device__ __forceinline__ uint32_t s2u(const void* p) {
    uint32_t a;
    asm("{ .reg .u64 t; cvta.to.shared.u64 t, %1; cvt.u32.u64 %0, t; }"
        : "=r"(a) : "l"(p));
    return a;
}

__device__ __forceinline__ void cp16(uint32_t dst, const void* src, int sz) {
    asm volatile("cp.async.cg.shared.global [%0], [%1], 16, %2;"
                 :: "r"(dst), "l"(src), "r"(sz) : "memory");
}

// load fp32 from smem, round-to-nearest-even into tf32 bit pattern
__device__ __forceinline__ uint32_t ld_tf32(const float* p) {
    uint32_t r;
    asm("cvt.rna.tf32.f32 %0, %1;" : "=r"(r) : "f"(*p));
    return r;
}

__global__ __launch_bounds__(256, 1)
void gemm_tc(const float* __restrict__ x,
             const float* __restrict__ Wl,
             const float* __restrict__ Wr,
             const float* __restrict__ bl,
             const float* __restrict__ br,
             float* __restrict__ out, int M) {
    extern __shared__ char smem[];
    const uint32_t sb = s2u(smem);
    float* smf = reinterpret_cast<float*>(smem);

    const int tid  = threadIdx.x;
    const int bm   = blockIdx.y * BM;
    const int bn   = blockIdx.x * BN;
    const int wid  = tid >> 5;
    const int lane = tid & 31;
    const int gid  = lane >> 2;        // 0..7
    const int tig  = lane & 3;         // 0..3
    const int wrow = wid >> 2;         // 0..1  -> 64-row slab
    const int wcol = wid & 3;          // 0..3  -> 32-col slab

    // bias into smem (BN=128 entries, first 128 threads only)
    if (tid < BN)
        smf[OFF_BIAS / 4 + tid] = bl[bn + tid] + br[bn + tid];

    // ---- stage loader: chunk t in 0..31 ; t<16 -> (x,Wl) ; else (agg,Wr)
    auto load_stage = [&](int t) {
        const int half = t >> 4;
        const int k0   = (t & 15) * BK;
        const float* A = half ? g_agg : x;
        const float* W = half ? Wr : Wl;
        const uint32_t abase = sb + (t % 3) * STAGE_B;
        const uint32_t bbase = abase + MAT_B;
#pragma unroll
        for (int i = 0; i < 4; i++) {
            const int c   = tid + i * 256;   // 0..1023
            const int row = c >> 3;          // 0..127
            const int kc  = c & 7;           // 16B chunk within 32-float row
            const uint32_t so = row * (PAD_K * 4) + kc * 16;
            cp16(abase + so, A + (size_t)(bm + row) * C_DIM + k0 + kc * 4,
                 (bm + row < M) ? 16 : 0);
            cp16(bbase + so, W + (size_t)(bn + row) * C_DIM + k0 + kc * 4, 16);
        }
        asm volatile("cp.async.commit_group;" ::: "memory");
    };

    float acc[4][4][4];
#pragma unroll
    for (int i = 0; i < 4; i++)
#pragma unroll
        for (int j = 0; j < 4; j++)
#pragma unroll
            for (int v = 0; v < 4; v++) acc[i][j][v] = 0.f;

    load_stage(0);
    load_stage(1);

#pragma unroll 1
    for (int s = 0; s < 32; s++) {
        asm volatile("cp.async.wait_group 1;" ::: "memory");
        __syncthreads();                       // stage s visible; buf (s+2)%3 free
        if (s + 2 < 32) load_stage(s + 2);
        else asm volatile("cp.async.commit_group;" ::: "memory");

        const float* As = smf + ((s % 3) * STAGE_B) / 4;
        const float* Bs = As + MAT_B / 4;
        // per-thread fragment bases (conflict-free: bank = (4*gid+tig)%32)
        const float* ap = As + (wrow * 64 + gid) * PAD_K + tig;
        const float* bp = Bs + (wcol * 32 + gid) * PAD_K + tig;

#pragma unroll
        for (int kk = 0; kk < 4; kk++) {       // 4 x (K=8)
            const int k = kk * 8;
            uint32_t a[4][4], b[4][2];
#pragma unroll
            for (int mt = 0; mt < 4; mt++) {
                const float* p = ap + mt * 16 * PAD_K + k;
                a[mt][0] = ld_tf32(p);
                a[mt][1] = ld_tf32(p + 8 * PAD_K);
                a[mt][2] = ld_tf32(p + 4);
                a[mt][3] = ld_tf32(p + 8 * PAD_K + 4);
            }
#pragma unroll
            for (int nt = 0; nt < 4; nt++) {
                const float* p = bp + nt * 8 * PAD_K + k;
                b[nt][0] = ld_tf32(p);
                b[nt][1] = ld_tf32(p + 4);
            }
#pragma unroll
            for (int mt = 0; mt < 4; mt++)
#pragma unroll
                for (int nt = 0; nt < 4; nt++) {
                    asm volatile(
                        "mma.sync.aligned.m16n8k8.row.col.f32.tf32.tf32.f32 "
                        "{%0,%1,%2,%3}, {%4,%5,%6,%7}, {%8,%9}, {%0,%1,%2,%3};"
                        : "+f"(acc[mt][nt][0]), "+f"(acc[mt][nt][1]),
                          "+f"(acc[mt][nt][2]), "+f"(acc[mt][nt][3])
                        : "r"(a[mt][0]), "r"(a[mt][1]),
                          "r"(a[mt][2]), "r"(a[mt][3]),
                          "r"(b[nt][0]), "r"(b[nt][1]));
                }
        }
    }
    asm volatile("cp.async.wait_group 0;" ::: "memory");

    // ---- epilogue: bias + store (float2 per d-pair)
    const float* bias = smf + OFF_BIAS / 4;
#pragma unroll
    for (int mt = 0; mt < 4; mt++) {
        const int r0 = bm + wrow * 64 + mt * 16 + gid;
        const int r1 = r0 + 8;
#pragma unroll
        for (int nt = 0; nt < 4; nt++) {
            const int col  = wcol * 32 + nt * 8 + 2 * tig;
            const float b0 = bias[col], b1 = bias[col + 1];
            if (r0 < M) {
                float2 v = make_float2(acc[mt][nt][0] + b0, acc[mt][nt][1] + b1);
                *reinterpret_cast<float2*>(out + (size_t)r0 * OUT_DIM + bn + col) = v;
            }
            if (r1 < M) {
                float2 v = make_float2(acc[mt][nt][2] + b0, acc[mt][nt][3] + b1);
                *reinterpret_cast<float2*>(out + (size_t)r1 * OUT_DIM + bn + col) = v;
            }
        }
    }
}

extern "C" void kernel_launch(void* const* d_in, const int* in_sizes, int n_in,
                              void* d_out, int out_size) {
    const float* x     = (const float*)d_in[0];
    const float* neigh = (const float*)d_in[1];
    const float* Wl    = (const float*)d_in[2];
    const float* bl    = (const float*)d_in[3];
    const float* Wr    = (const float*)d_in[4];
    const float* br    = (const float*)d_in[5];
    float* out         = (float*)d_out;

    const int M = in_sizes[0] / C_DIM;   // 20000

    cudaFuncSetAttribute(gemm_tc, cudaFuncAttributeMaxDynamicSharedMemorySize,
                         SMEM_TOTAL);

    mean_kernel<<<M, 128>>>(neigh, M);

    dim3 grid(OUT_DIM / BN, (M + BM - 1) / BM);
    gemm_tc<<<grid, 256, SMEM_TOTAL>>>(x, Wl, Wr, bl, br, out, M);
}

// round 11
// speedup vs baseline: 2.0927x; 1.0103x over previous
#include <cuda_runtime.h>
#include <cstdint>
#include <cstddef>

#define C_DIM   512
#define OUT_DIM 512
#define K_NEIGH 32
#define MAX_N   20000

// Scratch (allocation-free rule: __device__ global)
__device__ float g_agg[(size_t)MAX_N * C_DIM];

// ---------------------------------------------------------------------------
// Kernel 1: agg[n,c] = mean_k neigh[n,k,c]   (HBM-bound, streams 1.31 GB)
// ---------------------------------------------------------------------------
__global__ void mean_kernel(const float* __restrict__ neigh, int M) {
    int n = blockIdx.x;
    if (n >= M) return;
    int c4 = threadIdx.x;  // 0..127
    const float4* base = reinterpret_cast<const float4*>(neigh)
                       + (size_t)n * (K_NEIGH * C_DIM / 4) + c4;
    float4 s = make_float4(0.f, 0.f, 0.f, 0.f);
#pragma unroll
    for (int k = 0; k < K_NEIGH; ++k) {
        float4 v = base[(size_t)k * (C_DIM / 4)];
        s.x += v.x; s.y += v.y; s.z += v.z; s.w += v.w;
    }
    const float inv = 1.0f / (float)K_NEIGH;
    s.x *= inv; s.y *= inv; s.z *= inv; s.w *= inv;
    reinterpret_cast<float4*>(g_agg)[(size_t)n * (C_DIM / 4) + c4] = s;
}

// ---------------------------------------------------------------------------
// Kernel 2: tensor-core tf32 GEMM via mma.sync (m16n8k8).
//   out = [x | agg] @ [Wl | Wr]^T + (bl + br)
// CTA tile 128x128, BK=32, 3-stage cp.async ring, 8 warps (2x4), warp 64x32.
// Smem rows padded to 36 floats -> conflict-free fragment LDS.
// 2 CTAs/SM (smem 2x111KB fits 227KB carveout; 125 regs x 512 thr fits RF).
// ---------------------------------------------------------------------------
#define BM 128
#define BN 128
#define BK 32
#define PAD_K 36                       // floats per smem row (144 B)
#define MAT_B   (BM * PAD_K * 4)       // 18432 B per matrix
#define STAGE_B (2 * MAT_B)            // 36864 B per stage
#define OFF_BIAS (3 * STAGE_B)         // 110592
#define SMEM_TOTAL (OFF_BIAS + BN * 4) // 111104

__device__ __forceinline__ uint32_t s2u(const void* p) {
    uint32_t a;
    asm("{ .reg .u64 t; cvta.to.shared.u64 t, %1; cvt.u32.u64 %0, t; }"
        : "=r"(a) : "l"(p));
    return a;
}

__device__ __forceinline__ void cp16(uint32_t dst, const void* src, int sz) {
    asm volatile("cp.async.cg.shared.global [%0], [%1], 16, %2;"
                 :: "r"(dst), "l"(src), "r"(sz) : "memory");
}

// load fp32 from smem, round-to-nearest-even into tf32 bit pattern
__device__ __forceinline__ uint32_t ld_tf32(const float* p) {
    uint32_t r;
    asm("cvt.rna.tf32.f32 %0, %1;" : "=r"(r) : "f"(*p));
    return r;
}

__global__ __launch_bounds__(256, 2)
void gemm_tc(const float* __restrict__ x,
             const float* __restrict__ Wl,
             const float* __restrict__ Wr,
             const float* __restrict__ bl,
             const float* __restrict__ br,
             float* __restrict__ out, int M) {
    extern __shared__ char smem[];
    const uint32_t sb = s2u(smem);
    float* smf = reinterpret_cast<float*>(smem);

    const int tid  = threadIdx.x;
    const int bm   = blockIdx.y * BM;
    const int bn   = blockIdx.x * BN;
    const int wid  = tid >> 5;
    const int lane = tid & 31;
    const int gid  = lane >> 2;        // 0..7
    const int tig  = lane & 3;         // 0..3
    const int wrow = wid >> 2;         // 0..1  -> 64-row slab
    const int wcol = wid & 3;          // 0..3  -> 32-col slab

    // bias into smem (BN=128 entries, first 128 threads only)
    if (tid < BN)
        smf[OFF_BIAS / 4 + tid] = bl[bn + tid] + br[bn + tid];

    // ---- stage loader: chunk t in 0..31 ; t<16 -> (x,Wl) ; else (agg,Wr)
    auto load_stage = [&](int t) {
        const int half = t >> 4;
        const int k0   = (t & 15) * BK;
        const float* A = half ? g_agg : x;
        const float* W = half ? Wr : Wl;
        const uint32_t abase = sb + (t % 3) * STAGE_B;
        const uint32_t bbase = abase + MAT_B;
#pragma unroll
        for (int i = 0; i < 4; i++) {
            const int c   = tid + i * 256;   // 0..1023
            const int row = c >> 3;          // 0..127
            const int kc  = c & 7;           // 16B chunk within 32-float row
            const uint32_t so = row * (PAD_K * 4) + kc * 16;
            cp16(abase + so, A + (size_t)(bm + row) * C_DIM + k0 + kc * 4,
                 (bm + row < M) ? 16 : 0);
            cp16(bbase + so, W + (size_t)(bn + row) * C_DIM + k0 + kc * 4, 16);
        }
        asm volatile("cp.async.commit_group;" ::: "memory");
    };

    float acc[4][4][4];
#pragma unroll
    for (int i = 0; i < 4; i++)
#pragma unroll
        for (int j = 0; j < 4; j++)
#pragma unroll
            for (int v = 0; v < 4; v++) acc[i][j][v] = 0.f;

    load_stage(0);
    load_stage(1);

#pragma unroll 1
    for (int s = 0; s < 32; s++) {
        asm volatile("cp.async.wait_group 1;" ::: "memory");
        __syncthreads();                       // stage s visible; buf (s+2)%3 free
        if (s + 2 < 32) load_stage(s + 2);
        else asm volatile("cp.async.commit_group;" ::: "memory");

        const float* As = smf + ((s % 3) * STAGE_B) / 4;
        const float* Bs = As + MAT_B / 4;
        // per-thread fragment bases (conflict-free: bank = (4*gid+tig)%32)
        const float* ap = As + (wrow * 64 + gid) * PAD_K + tig;
        const float* bp = Bs + (wcol * 32 + gid) * PAD_K + tig;

#pragma unroll
        for (int kk = 0; kk < 4; kk++) {       // 4 x (K=8)
            const int k = kk * 8;
            uint32_t a[4][4], b[4][2];
#pragma unroll
            for (int mt = 0; mt < 4; mt++) {
                const float* p = ap + mt * 16 * PAD_K + k;
                a[mt][0] = ld_tf32(p);
                a[mt][1] = ld_tf32(p + 8 * PAD_K);
                a[mt][2] = ld_tf32(p + 4);
                a[mt][3] = ld_tf32(p + 8 * PAD_K + 4);
            }
#pragma unroll
            for (int nt = 0; nt < 4; nt++) {
                const float* p = bp + nt * 8 * PAD_K + k;
                b[nt][0] = ld_tf32(p);
                b[nt][1] = ld_tf32(p + 4);
            }
#pragma unroll
            for (int mt = 0; mt < 4; mt++)
#pragma unroll
                for (int nt = 0; nt < 4; nt++) {
                    asm volatile(
                        "mma.sync.aligned.m16n8k8.row.col.f32.tf32.tf32.f32 "
                        "{%0,%1,%2,%3}, {%4,%5,%6,%7}, {%8,%9}, {%0,%1,%2,%3};"
                        : "+f"(acc[mt][nt][0]), "+f"(acc[mt][nt][1]),
                          "+f"(acc[mt][nt][2]), "+f"(acc[mt][nt][3])
                        : "r"(a[mt][0]), "r"(a[mt][1]),
                          "r"(a[mt][2]), "r"(a[mt][3]),
                          "r"(b[nt][0]), "r"(b[nt][1]));
                }
        }
    }
    asm volatile("cp.async.wait_group 0;" ::: "memory");

    // ---- epilogue: bias + store (float2 per d-pair)
    const float* bias = smf + OFF_BIAS / 4;
#pragma unroll
    for (int mt = 0; mt < 4; mt++) {
        const int r0 = bm + wrow * 64 + mt * 16 + gid;
        const int r1 = r0 + 8;
#pragma unroll
        for (int nt = 0; nt < 4; nt++) {
            const int col  = wcol * 32 + nt * 8 + 2 * tig;
            const float b0 = bias[col], b1 = bias[col + 1];
            if (r0 < M) {
                float2 v = make_float2(acc[mt][nt][0] + b0, acc[mt][nt][1] + b1);
                *reinterpret_cast<float2*>(out + (size_t)r0 * OUT_DIM + bn + col) = v;
            }
            if (r1 < M) {
                float2 v = make_float2(acc[mt][nt][2] + b0, acc[mt][nt][3] + b1);
                *reinterpret_cast<float2*>(out + (size_t)r1 * OUT_DIM + bn + col) = v;
            }
        }
    }
}

extern "C" void kernel_launch(void* const* d_in, const int* in_sizes, int n_in,
                              void* d_out, int out_size) {
    const float* x     = (const float*)d_in[0];
    const float* neigh = (const float*)d_in[1];
    const float* Wl    = (const float*)d_in[2];
    const float* bl    = (const float*)d_in[3];
    const float* Wr    = (const float*)d_in[4];
    const float* br    = (const float*)d_in[5];
    float* out         = (float*)d_out;

    const int M = in_sizes[0] / C_DIM;   // 20000

    cudaFuncSetAttribute(gemm_tc, cudaFuncAttributeMaxDynamicSharedMemorySize,
                         SMEM_TOTAL);

    mean_kernel<<<M, 128>>>(neigh, M);

    dim3 grid(OUT_DIM / BN, (M + BM - 1) / BM);
    gemm_tc<<<grid, 256, SMEM_TOTAL>>>(x, Wl, Wr, bl, br, out, M);
}